// round 1
// baseline (speedup 1.0000x reference)
#include <cuda_runtime.h>

#define NROWS 32768
#define DIM   256
#define NC    8192

#define BM 64
#define BN 64
#define BK 32
#define AP 260   // A smem row pitch (floats), 260*4=1040B, 16B aligned
#define BP 68    // B smem row pitch (floats), 68*4=272B, 16B aligned

// ---------------- scratch (device globals; no allocations allowed) ----------
__device__ float g_sumz[NROWS];
__device__ float g_cnorm[NC];
__device__ int   g_idx[NROWS];
__device__ float g_count[NC];
__device__ float g_wsum[NC * DIM];
__device__ float g_loss;
__device__ float g_n;

// ---------------- zero scratch ----------------------------------------------
__global__ void k_zero() {
    int i = blockIdx.x * blockDim.x + threadIdx.x;
    int stride = gridDim.x * blockDim.x;
    for (int j = i; j < NC * DIM; j += stride) g_wsum[j] = 0.0f;
    if (i < NC) g_count[i] = 0.0f;
    if (i == 0) { g_loss = 0.0f; g_n = 0.0f; }
}

// ---------------- row sum of squares (strided lanes, mul then add — no FMA) -
__global__ void k_rownorm(const float* __restrict__ x, float* __restrict__ out, int rows) {
    int warp = (blockIdx.x * blockDim.x + threadIdx.x) >> 5;
    int lane = threadIdx.x & 31;
    if (warp >= rows) return;
    const float* row = x + (size_t)warp * DIM;
    float s = 0.0f;
#pragma unroll
    for (int m = 0; m < 8; m++) {
        float v = row[lane + 32 * m];
        s = __fadd_rn(s, __fmul_rn(v, v));
    }
#pragma unroll
    for (int o = 16; o > 0; o >>= 1)
        s = __fadd_rn(s, __shfl_down_sync(0xffffffffu, s, o));
    if (lane == 0) out[warp] = s;
}

// ---------------- distance GEMM + online argmin ------------------------------
// dists = fl(fl(sumz - 2*dot) + cnorm), dot accumulated with ordered-k fp32 FMA.
// Ties broken by lowest code index (matches jnp.argmin).
__global__ void k_argmin(const float* __restrict__ z, const float* __restrict__ cbw,
                         const float* __restrict__ sumz, const float* __restrict__ cnorm,
                         int* __restrict__ idx_out, float* __restrict__ idxf_out) {
    extern __shared__ float sm[];
    float* As = sm;               // [BM][AP] row-major (m, k), full K resident
    float* Bs = sm + BM * AP;     // [BK][BP] k-major (k, n)

    int t = threadIdx.x;
    int row0 = blockIdx.x * BM;

    // Load entire A tile (64 rows x 256 k) once: 4096 float4, 16 per thread
#pragma unroll
    for (int i = 0; i < 16; i++) {
        int p  = t + i * 256;
        int r  = p >> 6;
        int kq = p & 63;
        float4 v = *reinterpret_cast<const float4*>(z + (size_t)(row0 + r) * DIM + kq * 4);
        *reinterpret_cast<float4*>(As + r * AP + kq * 4) = v;
    }
    __syncthreads();

    int ty = t >> 4, tx = t & 15;
    int m0 = ty * 4, n0 = tx * 4;

    float szr[4];
#pragma unroll
    for (int i = 0; i < 4; i++) szr[i] = sumz[row0 + m0 + i];

    float bestv[4];
    int   besti[4];
#pragma unroll
    for (int i = 0; i < 4; i++) { bestv[i] = 3.4e38f; besti[i] = 0; }

    for (int cb0 = 0; cb0 < NC; cb0 += BN) {
        float acc[4][4];
#pragma unroll
        for (int i = 0; i < 4; i++)
#pragma unroll
            for (int j = 0; j < 4; j++) acc[i][j] = 0.0f;

        for (int kc = 0; kc < DIM; kc += BK) {
            // Load B tile (64 codes x 32 k), transpose into Bs[k][n]
#pragma unroll
            for (int q = 0; q < 2; q++) {
                int p  = t + q * 256;     // 0..511
                int r  = p >> 3;          // code 0..63
                int kq = p & 7;           // float4 within k-chunk
                float4 v = *reinterpret_cast<const float4*>(
                    cbw + (size_t)(cb0 + r) * DIM + kc + kq * 4);
                Bs[(kq * 4 + 0) * BP + r] = v.x;
                Bs[(kq * 4 + 1) * BP + r] = v.y;
                Bs[(kq * 4 + 2) * BP + r] = v.z;
                Bs[(kq * 4 + 3) * BP + r] = v.w;
            }
            __syncthreads();

#pragma unroll
            for (int k = 0; k < BK; k++) {
                float a0 = As[(m0 + 0) * AP + kc + k];
                float a1 = As[(m0 + 1) * AP + kc + k];
                float a2 = As[(m0 + 2) * AP + kc + k];
                float a3 = As[(m0 + 3) * AP + kc + k];
                float4 b = *reinterpret_cast<float4*>(Bs + k * BP + n0);
                acc[0][0] = __fmaf_rn(a0, b.x, acc[0][0]);
                acc[0][1] = __fmaf_rn(a0, b.y, acc[0][1]);
                acc[0][2] = __fmaf_rn(a0, b.z, acc[0][2]);
                acc[0][3] = __fmaf_rn(a0, b.w, acc[0][3]);
                acc[1][0] = __fmaf_rn(a1, b.x, acc[1][0]);
                acc[1][1] = __fmaf_rn(a1, b.y, acc[1][1]);
                acc[1][2] = __fmaf_rn(a1, b.z, acc[1][2]);
                acc[1][3] = __fmaf_rn(a1, b.w, acc[1][3]);
                acc[2][0] = __fmaf_rn(a2, b.x, acc[2][0]);
                acc[2][1] = __fmaf_rn(a2, b.y, acc[2][1]);
                acc[2][2] = __fmaf_rn(a2, b.z, acc[2][2]);
                acc[2][3] = __fmaf_rn(a2, b.w, acc[2][3]);
                acc[3][0] = __fmaf_rn(a3, b.x, acc[3][0]);
                acc[3][1] = __fmaf_rn(a3, b.y, acc[3][1]);
                acc[3][2] = __fmaf_rn(a3, b.z, acc[3][2]);
                acc[3][3] = __fmaf_rn(a3, b.w, acc[3][3]);
            }
            __syncthreads();
        }

        // Epilogue: d = fl(fl(sumz - 2*dot) + cnorm); strict < keeps lowest index
#pragma unroll
        for (int j = 0; j < 4; j++) {
            float cn = cnorm[cb0 + n0 + j];
#pragma unroll
            for (int i = 0; i < 4; i++) {
                float d = __fadd_rn(__fadd_rn(szr[i], -2.0f * acc[i][j]), cn);
                if (d < bestv[i]) { bestv[i] = d; besti[i] = cb0 + n0 + j; }
            }
        }
    }
    __syncthreads();

    // Cross-thread reduce (16 column-threads per row), tie -> lowest index
    float* rv = sm;                       // [64][16]
    int*   ri = (int*)(sm + 64 * 16);     // [64][16]
#pragma unroll
    for (int i = 0; i < 4; i++) {
        rv[(m0 + i) * 16 + tx] = bestv[i];
        ri[(m0 + i) * 16 + tx] = besti[i];
    }
    __syncthreads();
    if (t < 64) {
        float bv = rv[t * 16];
        int   bi = ri[t * 16];
#pragma unroll
        for (int x = 1; x < 16; x++) {
            float v  = rv[t * 16 + x];
            int   ii = ri[t * 16 + x];
            if (v < bv || (v == bv && ii < bi)) { bv = v; bi = ii; }
        }
        idx_out[row0 + t]  = bi;
        idxf_out[row0 + t] = (float)bi;
    }
}

// ---------------- scatter: counts, weight sums, loss partial, z_q ------------
__global__ void k_scatter(const float* __restrict__ z, const float* __restrict__ cbw,
                          const int* __restrict__ idx,
                          float* __restrict__ wsum, float* __restrict__ cnt,
                          float* __restrict__ lossacc, float* __restrict__ zq_out) {
    int warp = (blockIdx.x * blockDim.x + threadIdx.x) >> 5;
    int lane = threadIdx.x & 31;
    if (warp >= NROWS) return;
    int c = idx[warp];
    const float* zr = z   + (size_t)warp * DIM;
    const float* cr = cbw + (size_t)c    * DIM;
    float ls = 0.0f;
#pragma unroll
    for (int m = 0; m < 8; m++) {
        int d = lane + 32 * m;
        float zv = zr[d], cv = cr[d];
        atomicAdd(&wsum[c * DIM + d], zv);
        float diff = __fadd_rn(zv, -cv);             // fl(z - c)
        ls = __fadd_rn(ls, __fmul_rn(diff, diff));
        float st = __fadd_rn(cv, -zv);               // fl(c - z)
        zq_out[(size_t)warp * DIM + d] = __fadd_rn(zv, st);  // fl(z + fl(c - z))
    }
#pragma unroll
    for (int o = 16; o > 0; o >>= 1)
        ls = __fadd_rn(ls, __shfl_down_sync(0xffffffffu, ls, o));
    if (lane == 0) {
        atomicAdd(&cnt[c], 1.0f);
        atomicAdd(lossacc, ls);
    }
}

// ---------------- EMA count + n --------------------------------------------
__global__ void k_ema(const float* __restrict__ ema_count, const float* __restrict__ cnt,
                      float* __restrict__ out_count, float* __restrict__ n_acc) {
    int c = blockIdx.x * blockDim.x + threadIdx.x;
    float nec = 0.0f;
    if (c < NC) {
        nec = __fadd_rn(__fmul_rn(0.99f, ema_count[c]), __fmul_rn(0.01f, cnt[c]));
        out_count[c] = nec;
    }
    __shared__ float red[256];
    red[threadIdx.x] = nec;
    __syncthreads();
    for (int s = 128; s > 0; s >>= 1) {
        if (threadIdx.x < s) red[threadIdx.x] = __fadd_rn(red[threadIdx.x], red[threadIdx.x + s]);
        __syncthreads();
    }
    if (threadIdx.x == 0) atomicAdd(n_acc, red[0]);
}

// ---------------- new codebook + new ema weight ------------------------------
__global__ void k_codebook(const float* __restrict__ ema_weight, const float* __restrict__ wsum,
                           const float* __restrict__ out_count, const float* __restrict__ n_acc,
                           float* __restrict__ out_cb, float* __restrict__ out_ew) {
    size_t i = (size_t)blockIdx.x * 256 + threadIdx.x;
    if (i >= (size_t)NC * DIM) return;
    int c = (int)(i >> 8);
    float new_ew = __fadd_rn(__fmul_rn(0.99f, ema_weight[i]), __fmul_rn(0.01f, wsum[i]));
    out_ew[i] = new_ew;
    float n  = *n_acc;
    float a  = __fadd_rn(out_count[c], 1e-5f);
    float b  = __fadd_rn(n, 0.08192f);             // N_CODES * EPS in fp32
    float cs = __fmul_rn(__fdiv_rn(a, b), n);
    out_cb[i] = __fdiv_rn(new_ew, cs);
}

// ---------------- loss finalize ----------------------------------------------
__global__ void k_loss(const float* __restrict__ lossacc, float* __restrict__ out_loss) {
    float m = __fdiv_rn(*lossacc, 8388608.0f);     // mean over N*D (2^23, exact)
    *out_loss = __fmul_rn(0.25f, m);               // COMMITMENT_COST
}

// ---------------- launch ------------------------------------------------------
extern "C" void kernel_launch(void* const* d_in, const int* in_sizes, int n_in,
                              void* d_out, int out_size) {
    const float* z          = (const float*)d_in[0];
    const float* cbw        = (const float*)d_in[1];
    const float* ema_count  = (const float*)d_in[2];
    const float* ema_weight = (const float*)d_in[3];

    float* out      = (float*)d_out;
    float* out_zq   = out;                       // 8388608
    float* out_idx  = out + 8388608;             // 32768
    float* out_loss = out + 8421376;             // 1
    float* out_cb   = out + 8421377;             // 2097152
    float* out_cnt  = out + 10518529;            // 8192
    float* out_ew   = out + 10526721;            // 2097152

    float *p_sumz, *p_cnorm, *p_count, *p_wsum, *p_loss, *p_n;
    int* p_idx;
    cudaGetSymbolAddress((void**)&p_sumz,  g_sumz);
    cudaGetSymbolAddress((void**)&p_cnorm, g_cnorm);
    cudaGetSymbolAddress((void**)&p_idx,   g_idx);
    cudaGetSymbolAddress((void**)&p_count, g_count);
    cudaGetSymbolAddress((void**)&p_wsum,  g_wsum);
    cudaGetSymbolAddress((void**)&p_loss,  g_loss);
    cudaGetSymbolAddress((void**)&p_n,     g_n);

    const int smem_bytes = (BM * AP + BK * BP) * 4;   // 75264
    cudaFuncSetAttribute(k_argmin, cudaFuncAttributeMaxDynamicSharedMemorySize, smem_bytes);

    k_zero<<<2048, 256>>>();
    k_rownorm<<<4096, 256>>>(z,   p_sumz,  NROWS);
    k_rownorm<<<1024, 256>>>(cbw, p_cnorm, NC);
    k_argmin<<<NROWS / BM, 256, smem_bytes>>>(z, cbw, p_sumz, p_cnorm, p_idx, out_idx);
    k_scatter<<<4096, 256>>>(z, cbw, p_idx, p_wsum, p_count, p_loss, out_zq);
    k_ema<<<32, 256>>>(ema_count, p_count, out_cnt, p_n);
    k_codebook<<<8192, 256>>>(ema_weight, p_wsum, out_cnt, p_n, out_cb, out_ew);
    k_loss<<<1, 1>>>(p_loss, out_loss);
}